// round 1
// baseline (speedup 1.0000x reference)
#include <cuda_runtime.h>
#include <cuda_bf16.h>
#include <stdint.h>

// Problem dims
#define BATCH   4
#define T_SEQ   2048
#define D_MODEL 1024
#define D_FF    4096
#define M_TOTAL (BATCH * T_SEQ)   // 8192 rows

// ---------------- device scratch (no allocations allowed) ----------------
__device__ __nv_bfloat16 g_A[M_TOTAL * D_MODEL];        // spikes in bf16 (16 MB)
__device__ __nv_bfloat16 g_W1b[D_FF * D_MODEL];         // W1 in bf16     (8 MB)
__device__ float g_h[(size_t)M_TOTAL * D_FF];           // h = spikes@W1^T (128 MB)
__device__ int   g_count;
#define SPIKE_CAP (1 << 20)
__device__ int   g_list[SPIKE_CAP];

// ---------------- small helpers ----------------
__device__ __forceinline__ uint32_t smem_u32(const void* p) {
    return (uint32_t)__cvta_generic_to_shared(p);
}
__device__ __forceinline__ void cp_async16(uint32_t saddr, const void* gaddr) {
    asm volatile("cp.async.cg.shared.global [%0], [%1], 16;\n" :: "r"(saddr), "l"(gaddr));
}
__device__ __forceinline__ void cp_commit() {
    asm volatile("cp.async.commit_group;\n" ::);
}
template <int N>
__device__ __forceinline__ void cp_wait() {
    asm volatile("cp.async.wait_group %0;\n" :: "n"(N));
}
__device__ __forceinline__ void ldmatrix_x4(uint32_t* r, uint32_t addr) {
    asm volatile("ldmatrix.sync.aligned.m8n8.x4.shared.b16 {%0,%1,%2,%3}, [%4];\n"
                 : "=r"(r[0]), "=r"(r[1]), "=r"(r[2]), "=r"(r[3]) : "r"(addr));
}
__device__ __forceinline__ void mma_bf16(float* c, const uint32_t* a, const uint32_t* b) {
    asm volatile(
        "mma.sync.aligned.m16n8k16.row.col.f32.bf16.bf16.f32 "
        "{%0,%1,%2,%3}, {%4,%5,%6,%7}, {%8,%9}, {%0,%1,%2,%3};\n"
        : "+f"(c[0]), "+f"(c[1]), "+f"(c[2]), "+f"(c[3])
        : "r"(a[0]), "r"(a[1]), "r"(a[2]), "r"(a[3]), "r"(b[0]), "r"(b[1]));
}

// ---------------- conversion kernels ----------------
__global__ void cvt_spikes(const float* __restrict__ in) {
    int i = blockIdx.x * blockDim.x + threadIdx.x;
    int stride = gridDim.x * blockDim.x;
    int n = M_TOTAL * D_MODEL;
    for (; i < n; i += stride) g_A[i] = __float2bfloat16(in[i]);
}
__global__ void cvt_w1(const float* __restrict__ in) {
    int i = blockIdx.x * blockDim.x + threadIdx.x;
    int stride = gridDim.x * blockDim.x;
    int n = D_FF * D_MODEL;
    for (; i < n; i += stride) g_W1b[i] = __float2bfloat16(in[i]);
}

// ---------------- GEMM: h[m][n] = sum_k A[m][k] * W1[n][k] ----------------
// CTA tile 128x128, BK=32, 8 warps (2 along M x 4 along N), warp tile 64x32.
#define BK 32
#define SMEM_LD 40   // padded row stride (bf16 elements): 80B -> conflict-free ldmatrix

__global__ void __launch_bounds__(256) gemm_h_kernel() {
    __shared__ __nv_bfloat16 As[2][128 * SMEM_LD];
    __shared__ __nv_bfloat16 Bs[2][128 * SMEM_LD];

    const int tid  = threadIdx.x;
    const int lane = tid & 31;
    const int w    = tid >> 5;
    const int wm   = w & 1;        // 0..1 -> 64-row slab
    const int wn   = w >> 1;       // 0..3 -> 32-col slab
    const int m0   = blockIdx.y * 128;
    const int n0   = blockIdx.x * 128;

    float acc[4][4][4];
#pragma unroll
    for (int i = 0; i < 4; i++)
#pragma unroll
        for (int j = 0; j < 4; j++)
#pragma unroll
            for (int e = 0; e < 4; e++) acc[i][j][e] = 0.f;

    const int lrow = tid >> 2;          // 0..63
    const int lcol = (tid & 3) * 8;     // 0,8,16,24 (bf16 elems -> 16B chunks)

    auto load_tile = [&](int buf, int k0) {
        // A: rows m0+lrow and m0+lrow+64
        {
            const __nv_bfloat16* gp = g_A + (size_t)(m0 + lrow) * D_MODEL + k0 + lcol;
            uint32_t sp = smem_u32(&As[buf][lrow * SMEM_LD + lcol]);
            cp_async16(sp, gp);
            cp_async16(sp + 64 * SMEM_LD * 2, gp + (size_t)64 * D_MODEL);
        }
        // B: rows n0+lrow and n0+lrow+64
        {
            const __nv_bfloat16* gp = g_W1b + (size_t)(n0 + lrow) * D_MODEL + k0 + lcol;
            uint32_t sp = smem_u32(&Bs[buf][lrow * SMEM_LD + lcol]);
            cp_async16(sp, gp);
            cp_async16(sp + 64 * SMEM_LD * 2, gp + (size_t)64 * D_MODEL);
        }
    };

    auto compute = [&](int buf) {
#pragma unroll
        for (int kk = 0; kk < BK; kk += 16) {
            uint32_t a[4][4], b[4][2];
#pragma unroll
            for (int i = 0; i < 4; i++) {
                int arow = wm * 64 + i * 16 + (lane & 15);
                int acol = kk + (lane >> 4) * 8;
                ldmatrix_x4(a[i], smem_u32(&As[buf][arow * SMEM_LD + acol]));
            }
#pragma unroll
            for (int j = 0; j < 2; j++) {
                int brow = wn * 32 + j * 16 + (lane & 7) + ((lane >> 4) << 3);
                int bcol = kk + ((lane >> 3) & 1) * 8;
                uint32_t r[4];
                ldmatrix_x4(r, smem_u32(&Bs[buf][brow * SMEM_LD + bcol]));
                b[2 * j][0] = r[0]; b[2 * j][1] = r[1];
                b[2 * j + 1][0] = r[2]; b[2 * j + 1][1] = r[3];
            }
#pragma unroll
            for (int i = 0; i < 4; i++)
#pragma unroll
                for (int jn = 0; jn < 4; jn++)
                    mma_bf16(acc[i][jn], a[i], b[jn]);
        }
    };

    load_tile(0, 0);
    cp_commit();
    int cur = 0;
    const int KT = D_MODEL / BK;   // 32
    for (int kt = 0; kt < KT; kt++) {
        if (kt + 1 < KT) {
            load_tile(cur ^ 1, (kt + 1) * BK);
            cp_commit();
            cp_wait<1>();
        } else {
            cp_wait<0>();
        }
        __syncthreads();
        compute(cur);
        __syncthreads();
        cur ^= 1;
    }

    // epilogue: write fp32 h
#pragma unroll
    for (int i = 0; i < 4; i++) {
#pragma unroll
        for (int jn = 0; jn < 4; jn++) {
            int row = m0 + wm * 64 + i * 16 + (lane >> 2);
            int col = n0 + wn * 32 + jn * 8 + (lane & 3) * 2;
            float* hp = g_h + (size_t)row * D_FF + col;
            *reinterpret_cast<float2*>(hp) = make_float2(acc[i][jn][0], acc[i][jn][1]);
            hp += (size_t)8 * D_FF;
            *reinterpret_cast<float2*>(hp) = make_float2(acc[i][jn][2], acc[i][jn][3]);
        }
    }
}

// ---------------- misc kernels ----------------
__global__ void reset_count_kernel() {
    if (threadIdx.x == 0 && blockIdx.x == 0) g_count = 0;
}

__global__ void zero_out_kernel(float4* __restrict__ out, int n4) {
    int i = blockIdx.x * blockDim.x + threadIdx.x;
    int stride = gridDim.x * blockDim.x;
    float4 z = make_float4(0.f, 0.f, 0.f, 0.f);
    for (; i < n4; i += stride) out[i] = z;
}

// ---------------- temporal scan: EMA + threshold, append fired spikes ----------------
__global__ void scan_kernel() {
    int idx = blockIdx.x * blockDim.x + threadIdx.x;   // 0 .. 16383
    int b = idx >> 12;          // / 4096
    int f = idx & (D_FF - 1);
    const float* hp = g_h + (size_t)b * T_SEQ * D_FF + f;
    float mixed = 0.f;
    for (int t = 0; t < T_SEQ; t += 16) {
        float v[16];
#pragma unroll
        for (int i = 0; i < 16; i++) v[i] = hp[(size_t)(t + i) * D_FF];
#pragma unroll
        for (int i = 0; i < 16; i++) {
            mixed = 0.9f * mixed + 0.1f * v[i];
            if (mixed > 0.5f) {
                int pos = atomicAdd(&g_count, 1);
                if (pos < SPIKE_CAP)
                    g_list[pos] = (b * T_SEQ + (t + i)) * D_FF + f;
            }
        }
    }
}

// ---------------- sparse fixup: out[bt, :] += sigmoid(spikes[bt]·Wr[f]) * W2[:, f] ----------------
__global__ void fixup_kernel(const float* __restrict__ spikes,
                             const float* __restrict__ Wr,
                             const float* __restrict__ W2,
                             float* __restrict__ out) {
    __shared__ float red[256];
    int c = g_count;
    if (c > SPIKE_CAP) c = SPIKE_CAP;
    for (int i = blockIdx.x; i < c; i += gridDim.x) {
        int g  = g_list[i];
        int f  = g % D_FF;
        int bt = g / D_FF;
        const float* sp = spikes + (size_t)bt * D_MODEL;
        const float* wr = Wr + (size_t)f * D_MODEL;
        float s = 0.f;
        for (int d = threadIdx.x; d < D_MODEL; d += blockDim.x) s += sp[d] * wr[d];
        red[threadIdx.x] = s;
        __syncthreads();
        for (int o = 128; o > 0; o >>= 1) {
            if (threadIdx.x < o) red[threadIdx.x] += red[threadIdx.x + o];
            __syncthreads();
        }
        float rv = 1.f / (1.f + expf(-red[0]));
        float* op = out + (size_t)bt * D_MODEL;
        for (int d = threadIdx.x; d < D_MODEL; d += blockDim.x)
            atomicAdd(&op[d], rv * W2[(size_t)d * D_FF + f]);
        __syncthreads();
    }
}

// ---------------- launch ----------------
extern "C" void kernel_launch(void* const* d_in, const int* in_sizes, int n_in,
                              void* d_out, int out_size) {
    const float* spikes = (const float*)d_in[0];  // [B, T, D]
    // d_in[1] = W1 [F, D]  (consumed via cvt_w1)
    const float* W2 = (const float*)d_in[2];      // [D, F]
    const float* Wr = (const float*)d_in[3];      // [F, D]
    float* out = (float*)d_out;

    cvt_spikes<<<4096, 256>>>(spikes);
    cvt_w1<<<2048, 256>>>((const float*)d_in[1]);

    dim3 grid(D_FF / 128, M_TOTAL / 128);         // (32, 64)
    gemm_h_kernel<<<grid, 256>>>();

    reset_count_kernel<<<1, 32>>>();
    zero_out_kernel<<<2048, 256>>>((float4*)out, out_size / 4);

    scan_kernel<<<(BATCH * D_FF) / 256, 256>>>(); // 64 CTAs x 256

    fixup_kernel<<<128, 256>>>(spikes, Wr, W2, out);
}

// round 3
// speedup vs baseline: 1.4176x; 1.4176x over previous
#include <cuda_runtime.h>
#include <cuda_bf16.h>
#include <stdint.h>

// ---------------- problem dims ----------------
#define BATCH   4
#define T_SEQ   2048
#define D_MODEL 1024
#define D_FF    4096
#define M_TOTAL (BATCH * T_SEQ)   // 8192

// ---------------- device scratch ----------------
__device__ __nv_bfloat16 g_E[M_TOTAL * D_MODEL];    // ema(spikes) bf16 (16 MB)
__device__ __nv_bfloat16 g_W1b[D_FF * D_MODEL];     // W1 bf16          (8 MB)
__device__ int   g_count;
#define SPIKE_CAP (1 << 20)
__device__ int   g_list[SPIKE_CAP];

// ---------------- helpers ----------------
__device__ __forceinline__ uint32_t smem_u32(const void* p) {
    return (uint32_t)__cvta_generic_to_shared(p);
}
__device__ __forceinline__ void cp_async16(uint32_t saddr, const void* gaddr) {
    asm volatile("cp.async.cg.shared.global [%0], [%1], 16;\n" :: "r"(saddr), "l"(gaddr));
}
__device__ __forceinline__ void cp_commit() {
    asm volatile("cp.async.commit_group;\n" ::);
}
template <int N>
__device__ __forceinline__ void cp_wait() {
    asm volatile("cp.async.wait_group %0;\n" :: "n"(N));
}
__device__ __forceinline__ void ldmatrix_x4(uint32_t* r, uint32_t addr) {
    asm volatile("ldmatrix.sync.aligned.m8n8.x4.shared.b16 {%0,%1,%2,%3}, [%4];\n"
                 : "=r"(r[0]), "=r"(r[1]), "=r"(r[2]), "=r"(r[3]) : "r"(addr));
}
__device__ __forceinline__ void mma_bf16(float* c, const uint32_t* a, const uint32_t* b) {
    asm volatile(
        "mma.sync.aligned.m16n8k16.row.col.f32.bf16.bf16.f32 "
        "{%0,%1,%2,%3}, {%4,%5,%6,%7}, {%8,%9}, {%0,%1,%2,%3};\n"
        : "+f"(c[0]), "+f"(c[1]), "+f"(c[2]), "+f"(c[3])
        : "r"(a[0]), "r"(a[1]), "r"(a[2]), "r"(a[3]), "r"(b[0]), "r"(b[1]));
}

// ---------------- W1 fp32 -> bf16 ----------------
__global__ void cvt_w1(const float4* __restrict__ in) {
    int i = blockIdx.x * blockDim.x + threadIdx.x;
    int stride = gridDim.x * blockDim.x;
    int n4 = (D_FF * D_MODEL) / 4;
    uint2* out = reinterpret_cast<uint2*>(g_W1b);
    for (; i < n4; i += stride) {
        float4 v = in[i];
        uint32_t p0, p1;
        asm("cvt.rn.bf16x2.f32 %0, %1, %2;" : "=r"(p0) : "f"(v.y), "f"(v.x));
        asm("cvt.rn.bf16x2.f32 %0, %1, %2;" : "=r"(p1) : "f"(v.w), "f"(v.z));
        out[i] = make_uint2(p0, p1);
    }
}

// ---------------- EMA pre-scan over time (per (b,d) channel), chunked + halo ----------------
// mixed[b,t,f] = W1[f,:] . ema(spikes)[b,t,:]  (EMA commutes with the linear layer)
// 4096 chains x 2048 steps; 4 chunks of 512 with a 256-step halo (0.9^256 ~ 2e-12).
__global__ void __launch_bounds__(256) ema_kernel(const float* __restrict__ spikes) {
    int idx = blockIdx.x * 256 + threadIdx.x;     // 0 .. 16383
    int d  = idx & (D_MODEL - 1);
    int bc = idx >> 10;                           // 0..15
    int b  = bc >> 2;
    int c  = bc & 3;
    const float* sp = spikes + (size_t)b * T_SEQ * D_MODEL + d;
    __nv_bfloat16* ep = g_E + (size_t)b * T_SEQ * D_MODEL + d;
    int t0 = c * 512;
    float acc = 0.f;
    if (c) {
        for (int t = t0 - 256; t < t0; t += 8) {
            float v[8];
#pragma unroll
            for (int i = 0; i < 8; i++) v[i] = sp[(size_t)(t + i) * D_MODEL];
#pragma unroll
            for (int i = 0; i < 8; i++) acc = fmaf(0.9f, acc, 0.1f * v[i]);
        }
    }
    for (int t = t0; t < t0 + 512; t += 8) {
        float v[8];
#pragma unroll
        for (int i = 0; i < 8; i++) v[i] = sp[(size_t)(t + i) * D_MODEL];
#pragma unroll
        for (int i = 0; i < 8; i++) {
            acc = fmaf(0.9f, acc, 0.1f * v[i]);
            ep[(size_t)(t + i) * D_MODEL] = __float2bfloat16(acc);
        }
    }
}

__global__ void reset_count_kernel() {
    if (threadIdx.x == 0 && blockIdx.x == 0) g_count = 0;
}

// ---------------- GEMM: mixed[m][n] = sum_k E[m][k] * W1[n][k], threshold epilogue ----------------
// CTA tile 128x128, BK=32, 8 warps (2 along M x 4 along N), warp tile 64x32. (round-1 proven)
#define BK 32
#define SMEM_LD 40   // padded row stride (bf16): conflict-free ldmatrix

__global__ void __launch_bounds__(256) gemm_mixed_kernel() {
    __shared__ __nv_bfloat16 As[2][128 * SMEM_LD];
    __shared__ __nv_bfloat16 Bs[2][128 * SMEM_LD];

    const int tid  = threadIdx.x;
    const int lane = tid & 31;
    const int w    = tid >> 5;
    const int wm   = w & 1;
    const int wn   = w >> 1;
    const int m0   = blockIdx.y * 128;
    const int n0   = blockIdx.x * 128;

    float acc[4][4][4];
#pragma unroll
    for (int i = 0; i < 4; i++)
#pragma unroll
        for (int j = 0; j < 4; j++)
#pragma unroll
            for (int e = 0; e < 4; e++) acc[i][j][e] = 0.f;

    const int lrow = tid >> 2;
    const int lcol = (tid & 3) * 8;

    auto load_tile = [&](int buf, int k0) {
        {
            const __nv_bfloat16* gp = g_E + (size_t)(m0 + lrow) * D_MODEL + k0 + lcol;
            uint32_t sp = smem_u32(&As[buf][lrow * SMEM_LD + lcol]);
            cp_async16(sp, gp);
            cp_async16(sp + 64 * SMEM_LD * 2, gp + (size_t)64 * D_MODEL);
        }
        {
            const __nv_bfloat16* gp = g_W1b + (size_t)(n0 + lrow) * D_MODEL + k0 + lcol;
            uint32_t sp = smem_u32(&Bs[buf][lrow * SMEM_LD + lcol]);
            cp_async16(sp, gp);
            cp_async16(sp + 64 * SMEM_LD * 2, gp + (size_t)64 * D_MODEL);
        }
    };

    auto compute = [&](int buf) {
#pragma unroll
        for (int kk = 0; kk < BK; kk += 16) {
            uint32_t a[4][4], b[4][2];
#pragma unroll
            for (int i = 0; i < 4; i++) {
                int arow = wm * 64 + i * 16 + (lane & 15);
                int acol = kk + (lane >> 4) * 8;
                ldmatrix_x4(a[i], smem_u32(&As[buf][arow * SMEM_LD + acol]));
            }
#pragma unroll
            for (int j = 0; j < 2; j++) {
                int brow = wn * 32 + j * 16 + (lane & 7) + ((lane >> 4) << 3);
                int bcol = kk + ((lane >> 3) & 1) * 8;
                uint32_t r[4];
                ldmatrix_x4(r, smem_u32(&Bs[buf][brow * SMEM_LD + bcol]));
                b[2 * j][0] = r[0]; b[2 * j][1] = r[1];
                b[2 * j + 1][0] = r[2]; b[2 * j + 1][1] = r[3];
            }
#pragma unroll
            for (int i = 0; i < 4; i++)
#pragma unroll
                for (int jn = 0; jn < 4; jn++)
                    mma_bf16(acc[i][jn], a[i], b[jn]);
        }
    };

    load_tile(0, 0);
    cp_commit();
    int cur = 0;
    const int KT = D_MODEL / BK;   // 32
    for (int kt = 0; kt < KT; kt++) {
        if (kt + 1 < KT) {
            load_tile(cur ^ 1, (kt + 1) * BK);
            cp_commit();
            cp_wait<1>();
        } else {
            cp_wait<0>();
        }
        __syncthreads();
        compute(cur);
        __syncthreads();
        cur ^= 1;
    }

    // epilogue: threshold accumulators directly (no h materialization at all)
#pragma unroll
    for (int i = 0; i < 4; i++) {
#pragma unroll
        for (int jn = 0; jn < 4; jn++) {
            int row = m0 + wm * 64 + i * 16 + (lane >> 2);
            int col = n0 + wn * 32 + jn * 8 + (lane & 3) * 2;
#pragma unroll
            for (int e = 0; e < 4; e++) {
                if (acc[i][jn][e] > 0.5f) {
                    int r = row + (e >> 1) * 8;
                    int c = col + (e & 1);
                    int pos = atomicAdd(&g_count, 1);
                    if (pos < SPIKE_CAP) g_list[pos] = r * D_FF + c;
                }
            }
        }
    }
}

// ---------------- sparse fixup (exact; expected empty) ----------------
// out[bt, :] += sigmoid(spikes[bt]·Wr[f]) * W2[:, f] for each fired (bt, f)
__global__ void fixup_kernel(const float* __restrict__ spikes,
                             const float* __restrict__ Wr,
                             const float* __restrict__ W2,
                             float* __restrict__ out) {
    __shared__ float red[256];
    int c = g_count;
    if (c > SPIKE_CAP) c = SPIKE_CAP;
    for (int i = blockIdx.x; i < c; i += gridDim.x) {
        int g  = g_list[i];
        int f  = g % D_FF;
        int bt = g / D_FF;
        const float* sp = spikes + (size_t)bt * D_MODEL;
        const float* wr = Wr + (size_t)f * D_MODEL;
        float s = 0.f;
        for (int d = threadIdx.x; d < D_MODEL; d += blockDim.x) s += sp[d] * wr[d];
        red[threadIdx.x] = s;
        __syncthreads();
        for (int o = 128; o > 0; o >>= 1) {
            if (threadIdx.x < o) red[threadIdx.x] += red[threadIdx.x + o];
            __syncthreads();
        }
        float rv = 1.f / (1.f + expf(-red[0]));
        float* op = out + (size_t)bt * D_MODEL;
        for (int d = threadIdx.x; d < D_MODEL; d += blockDim.x)
            atomicAdd(&op[d], rv * W2[(size_t)d * D_FF + f]);
        __syncthreads();
    }
}

// ---------------- launch ----------------
extern "C" void kernel_launch(void* const* d_in, const int* in_sizes, int n_in,
                              void* d_out, int out_size) {
    const float* spikes = (const float*)d_in[0];  // [B, T, D]
    const float* W2 = (const float*)d_in[2];      // [D, F]
    const float* Wr = (const float*)d_in[3];      // [F, D]
    float* out = (float*)d_out;

    cvt_w1<<<1024, 256>>>((const float4*)d_in[1]);
    ema_kernel<<<64, 256>>>(spikes);
    reset_count_kernel<<<1, 32>>>();

    dim3 grid(D_FF / 128, M_TOTAL / 128);         // (32, 64)
    gemm_mixed_kernel<<<grid, 256>>>();           // kernel launch index 3

    cudaMemsetAsync(d_out, 0, (size_t)out_size * sizeof(float), 0);
    fixup_kernel<<<128, 256>>>(spikes, Wr, W2, out);
}